// round 13
// baseline (speedup 1.0000x reference)
#include <cuda_runtime.h>
#include <cuda_fp16.h>
#include <cstdint>
#include <cstring>

#define FEAT 2048
#define NCLS 751
#define NCLSP 768          // padded classes (6 tiles of 128)
#define NP   64
#define NG   256
#define NROWS (NP * NG)    // 16384
#define EPSV 1e-5f
#define WSCALE 512.0f
#define OSCALE (1.0f / 512.0f)

// GEMM tiling
#define TM   128
#define TNC  128
#define KT   64
#define KITERS (FEAT / KT) // 32
#define NKBLK (FEAT / 16)  // 128 fragment k-blocks

// SMEM: per stage: B only 16K; 4 stages + 1K align pad
#define STAGE_BYTES 16384
#define NSTAGE 4
#define SMEM_TOTAL (NSTAGE * STAGE_BYTES + 1024)

// --------------------------- device scratch --------------------------------
__device__ float d_scale[FEAT];
__device__ float d_shift[FEAT];
__device__ float d_C[NCLSP];
__device__ uint4 d_Wp16[NCLSP * (FEAT / 8)];        // fp16 W'*512
// A in MMA-fragment-major layout: [nblk 1024][kblk 128][lane 32] x 16B
__device__ uint4 d_A16f[(NROWS / 16) * NKBLK * 32]; // 64MB

// --------------------------- helpers ----------------------------------------
__device__ __forceinline__ uint32_t smem_u32(const void* p) {
    uint32_t a;
    asm("{ .reg .u64 t; cvta.to.shared.u64 t, %1; cvt.u32.u64 %0, t; }"
        : "=r"(a) : "l"(p));
    return a;
}
__device__ __forceinline__ void ldsm4(uint32_t* r, uint32_t addr) {
    asm volatile("ldmatrix.sync.aligned.m8n8.x4.shared.b16 {%0,%1,%2,%3}, [%4];"
                 : "=r"(r[0]), "=r"(r[1]), "=r"(r[2]), "=r"(r[3]) : "r"(addr));
}
__device__ __forceinline__ void mma16816(float* c, const uint32_t* a,
                                         const uint32_t* b) {
    asm volatile(
        "mma.sync.aligned.m16n8k16.row.col.f32.f16.f16.f32 "
        "{%0,%1,%2,%3}, {%4,%5,%6,%7}, {%8,%9}, {%0,%1,%2,%3};"
        : "+f"(c[0]), "+f"(c[1]), "+f"(c[2]), "+f"(c[3])
        : "r"(a[0]), "r"(a[1]), "r"(a[2]), "r"(a[3]), "r"(b[0]), "r"(b[1]));
}
__device__ __forceinline__ uint32_t pack16(float v0, float v1) {
    __half2 h = __float22half2_rn(make_float2(v0, v1));
    uint32_t u; memcpy(&u, &h, 4); return u;
}
__device__ __forceinline__ void cp16(uint32_t dst, const void* src) {
    asm volatile("cp.async.cg.shared.global [%0], [%1], 16;"
                 :: "r"(dst), "l"(src) : "memory");
}
__device__ __forceinline__ void cp_commit() {
    asm volatile("cp.async.commit_group;" ::: "memory");
}
__device__ __forceinline__ void cp_wait2() {
    asm volatile("cp.async.wait_group 2;" ::: "memory");
}

// ---------------------------------------------------------------------------
// Stage A: exact batch stats from per-feature moments. 128 blocks.
// ---------------------------------------------------------------------------
__global__ void stats_kernel(const float* __restrict__ probe,
                             const float* __restrict__ gallery,
                             const float* __restrict__ gamma,
                             const float* __restrict__ beta)
{
    const int tx = threadIdx.x & 15;
    const int ty = threadIdx.x >> 4;
    const int f  = blockIdx.x * 16 + tx;

    float p1 = 0, p2 = 0, p3 = 0, p4 = 0;
    #pragma unroll
    for (int i = ty * 4; i < ty * 4 + 4; i++) {
        float x = probe[i * FEAT + f];
        float x2 = x * x;
        p1 += x; p2 += x2; p3 += x2 * x; p4 += x2 * x2;
    }
    float g1 = 0, g2 = 0, g3 = 0, g4 = 0;
    #pragma unroll
    for (int j = ty * 16; j < ty * 16 + 16; j++) {
        float x = gallery[j * FEAT + f];
        float x2 = x * x;
        g1 += x; g2 += x2; g3 += x2 * x; g4 += x2 * x2;
    }

    __shared__ float red[8][16][16];
    red[0][ty][tx] = p1; red[1][ty][tx] = p2;
    red[2][ty][tx] = p3; red[3][ty][tx] = p4;
    red[4][ty][tx] = g1; red[5][ty][tx] = g2;
    red[6][ty][tx] = g3; red[7][ty][tx] = g4;
    __syncthreads();
    if (ty != 0) return;

    float m[8];
    #pragma unroll
    for (int q = 0; q < 8; q++) {
        float s = 0.f;
        #pragma unroll
        for (int t = 0; t < 16; t++) s += red[q][t][tx];
        m[q] = s;
    }
    p1 = m[0] * (1.f/NP); p2 = m[1] * (1.f/NP);
    p3 = m[2] * (1.f/NP); p4 = m[3] * (1.f/NP);
    g1 = m[4] * (1.f/NG); g2 = m[5] * (1.f/NG);
    g3 = m[6] * (1.f/NG); g4 = m[7] * (1.f/NG);

    float mean = p2 - 2.f * p1 * g1 + g2;
    float ed2  = p4 - 4.f * p3 * g1 + 6.f * p2 * g2 - 4.f * p1 * g3 + g4;
    float var  = ed2 - mean * mean;
    float s    = gamma[f] * rsqrtf(var + EPSV);
    d_scale[f] = s;
    d_shift[f] = beta[f] - mean * s;
}

// ---------------------------------------------------------------------------
// Stage A2: materialize A = (p-g)^2 as fp16 in MMA-fragment-major layout.
// Fragment (nblk, kblk), lane l holds (per m16n8k16 A spec):
//   u32[0] = rows n0+r,   k 2c..2c+1      u32[1] = rows n0+r+8, k 2c..2c+1
//   u32[2] = rows n0+r,   k 2c+8..2c+9    u32[3] = rows n0+r+8, k 2c+8..2c+9
// with r = l>>2, c = l&3.
// ---------------------------------------------------------------------------
__global__ __launch_bounds__(256)
void build_kernel(const float* __restrict__ probe,
                  const float* __restrict__ gallery)
{
    const int nblk = blockIdx.x;            // 0..1023
    const int lane = threadIdx.x & 31;
    const int kb0  = threadIdx.x >> 5;      // 0..7
    const int n0   = nblk * 16;
    const int i    = n0 >> 8;
    const int j0   = n0 & 255;
    const int r    = lane >> 2;
    const int c2   = (lane & 3) * 2;

    const float* pR = probe   + (size_t)i * FEAT;
    const float* gA = gallery + (size_t)(j0 + r) * FEAT;
    const float* gB = gallery + (size_t)(j0 + r + 8) * FEAT;
    uint4* dst = d_A16f + (size_t)nblk * NKBLK * 32 + lane;

    #pragma unroll 4
    for (int kb = kb0; kb < NKBLK; kb += 8) {
        const int k0 = kb * 16 + c2;
        const float2 pa = *(const float2*)(pR + k0);
        const float2 pb = *(const float2*)(pR + k0 + 8);
        const float2 ga = *(const float2*)(gA + k0);
        const float2 gb = *(const float2*)(gA + k0 + 8);
        const float2 ha = *(const float2*)(gB + k0);
        const float2 hb = *(const float2*)(gB + k0 + 8);
        float v0 = pa.x - ga.x; v0 *= v0;
        float v1 = pa.y - ga.y; v1 *= v1;
        float w0 = pa.x - ha.x; w0 *= w0;
        float w1 = pa.y - ha.y; w1 *= w1;
        float v2 = pb.x - gb.x; v2 *= v2;
        float v3 = pb.y - gb.y; v3 *= v3;
        float w2 = pb.x - hb.x; w2 *= w2;
        float w3 = pb.y - hb.y; w3 *= w3;
        dst[(size_t)kb * 32] = make_uint4(pack16(v0, v1), pack16(w0, w1),
                                          pack16(v2, v3), pack16(w2, w3));
    }
}

// ---------------------------------------------------------------------------
// Stage B: W'[c] = W[c]*scale*512 -> fp16 ; C[c] = b[c] + shift . W[c]
// ---------------------------------------------------------------------------
__global__ void prep_kernel(const float* __restrict__ W,
                            const float* __restrict__ b)
{
    int c = blockIdx.x;
    int t = threadIdx.x;
    if (c >= NCLS) {
        d_Wp16[c * 256 + t] = make_uint4(0, 0, 0, 0);
        if (t == 0) d_C[c] = 0.f;
        return;
    }
    int f0 = t * 8;
    const float4* wp = (const float4*)(W + (size_t)c * FEAT + f0);
    const float4* sp = (const float4*)(d_scale + f0);
    const float4* hp = (const float4*)(d_shift + f0);
    float4 w0 = wp[0], w1 = wp[1];
    float4 s0 = sp[0], s1 = sp[1];
    float4 h0 = hp[0], h1 = hp[1];

    float v0 = w0.x * s0.x * WSCALE, v1 = w0.y * s0.y * WSCALE;
    float v2 = w0.z * s0.z * WSCALE, v3 = w0.w * s0.w * WSCALE;
    float v4 = w1.x * s1.x * WSCALE, v5 = w1.y * s1.y * WSCALE;
    float v6 = w1.z * s1.z * WSCALE, v7 = w1.w * s1.w * WSCALE;
    d_Wp16[c * 256 + t] = make_uint4(pack16(v0, v1), pack16(v2, v3),
                                     pack16(v4, v5), pack16(v6, v7));

    float acc = w0.x*h0.x + w0.y*h0.y + w0.z*h0.z + w0.w*h0.w
              + w1.x*h1.x + w1.y*h1.y + w1.z*h1.z + w1.w*h1.w;
    #pragma unroll
    for (int o = 16; o > 0; o >>= 1)
        acc += __shfl_down_sync(0xFFFFFFFFu, acc, o);
    __shared__ float red[8];
    if ((t & 31) == 0) red[t >> 5] = acc;
    __syncthreads();
    if (t == 0) {
        float s = 0.f;
        #pragma unroll
        for (int w = 0; w < 8; w++) s += red[w];
        d_C[c] = b[c] + s;
    }
}

// ---------------------------------------------------------------------------
// Stage C: fp16 mma.sync GEMM. A fragments direct from gmem (LDG.128,
// L2-resident, L1-hit on 4x intra-CTA reuse); B via 4-stage cp.async + ldsm.
// 512 threads, 16 warps, 32x32 warp tiles, 2 CTAs/SM.
// ---------------------------------------------------------------------------
__global__ __launch_bounds__(512, 2)
void gemm_kernel(float* __restrict__ out)
{
    extern __shared__ char smem_raw[];
    char* smem = (char*)(((uintptr_t)smem_raw + 1023) & ~(uintptr_t)1023);
    const uint32_t sbase = smem_u32(smem);

    const int tid  = threadIdx.x;
    const int wid  = tid >> 5;            // 0..15
    const int lane = tid & 31;

    const int by    = blockIdx.y;
    const int ibase = (by >> 2) * 2;
    const int jbase = (by & 3) * 64;
    const int cbase = blockIdx.x * TNC;

    // ---- B staging mapping: thread -> (tile row rB, k-chunk h) ----
    const int rB = tid >> 2;              // 0..127
    const int h  = tid & 3;               // 16B chunk 0..3 (and +4)
    const uint4* wRow = d_Wp16 + (size_t)(cbase + rB) * 256 + h;
    uint32_t swzB0, swzB1;
    {
        const uint32_t o0 = (uint32_t)(rB * 128 + h * 16);
        const uint32_t o1 = o0 + 64;
        swzB0 = o0 ^ ((o0 >> 3) & 0x70u);
        swzB1 = o1 ^ ((o1 >> 3) & 0x70u);
    }

    // ---- mma mapping: warp grid 4(m) x 4(n); warp tile 32x32 ----
    const int m0 = (wid >> 2) * 32;
    const int n0 = (wid & 3) * 32;
    const int xr = (lane & 7) * 16;
    const int g  = lane >> 3;             // ldsm4 lane group 0..3

    // A fragment base pointers (fragment-major gmem layout)
    const int half = (m0 >= 64) ? 1 : 0;
    const int mlr  = m0 - half * 64;      // row within 64-half
    const int nb0  = (((ibase + half) * 256) + jbase + mlr) >> 4;
    const uint4* aF0 = d_A16f + (size_t)nb0 * NKBLK * 32 + lane;
    const uint4* aF1 = aF0 + (size_t)NKBLK * 32;   // +16 rows -> nblk+1

    uint32_t brow4[2], bkb4[4];
    #pragma unroll
    for (int p = 0; p < 2; p++)
        brow4[p] = (uint32_t)((n0 + (2 * p + (g >> 1)) * 8 + (lane & 7)) * 128);
    #pragma unroll
    for (int kk = 0; kk < 4; kk++)
        bkb4[kk] = (uint32_t)((kk * 32 + (g & 1) * 16) ^ xr);

    float acc[2][4][4];
    #pragma unroll
    for (int mt = 0; mt < 2; mt++)
        #pragma unroll
        for (int nt = 0; nt < 4; nt++)
            #pragma unroll
            for (int q = 0; q < 4; q++) acc[mt][nt][q] = 0.f;

    // ---- prologue: B stages 0..2 ----
    #pragma unroll
    for (int s = 0; s < 3; s++) {
        const uint32_t bd = sbase + s * STAGE_BYTES;
        const uint4* wp = wRow + s * 8;
        cp16(bd + swzB0, wp);
        cp16(bd + swzB1, wp + 4);
        cp_commit();
    }

    // ---- fully unrolled main loop ----
    #pragma unroll
    for (int kt = 0; kt < KITERS; kt++) {
        const int buf  = kt % NSTAGE;
        const int nbuf = (kt + 3) % NSTAGE;

        cp_wait2();                   // B stage kt resident (kt+1, kt+2 in flight)
        __syncthreads();

        if (kt + 3 < KITERS) {
            const uint32_t bd = sbase + nbuf * STAGE_BYTES;
            const uint4* wp = wRow + (kt + 3) * 8;
            cp16(bd + swzB0, wp);
            cp16(bd + swzB1, wp + 4);
        }
        cp_commit();

        const uint32_t sb = sbase + buf * STAGE_BYTES;
        #pragma unroll
        for (int kk = 0; kk < 4; kk++) {
            const int ko = kt * 4 + kk;     // compile-time after unroll
            // A fragments: direct LDG.128 (L1/L2-cached, no crossbar)
            const uint4 a0 = __ldg(aF0 + (size_t)ko * 32);
            const uint4 a1 = __ldg(aF1 + (size_t)ko * 32);
            uint32_t bfa[4], bfb[4];
            ldsm4(bfa, sb + brow4[0] + bkb4[kk]);   // nt 0,1
            ldsm4(bfb, sb + brow4[1] + bkb4[kk]);   // nt 2,3
            const uint32_t* ah0 = (const uint32_t*)&a0;
            const uint32_t* ah1 = (const uint32_t*)&a1;
            mma16816(acc[0][0], ah0, &bfa[0]);
            mma16816(acc[0][1], ah0, &bfa[2]);
            mma16816(acc[0][2], ah0, &bfb[0]);
            mma16816(acc[0][3], ah0, &bfb[2]);
            mma16816(acc[1][0], ah1, &bfa[0]);
            mma16816(acc[1][1], ah1, &bfa[2]);
            mma16816(acc[1][2], ah1, &bfb[0]);
            mma16816(acc[1][3], ah1, &bfb[2]);
        }
    }

    // ---- epilogue ----
    #pragma unroll
    for (int mt = 0; mt < 2; mt++) {
        const int mlA = m0 + mt * 16 + (lane >> 2);
        const int mlB = mlA + 8;
        const size_t nA = (size_t)((ibase + (mlA >> 6)) * NG + jbase + (mlA & 63));
        const size_t nB = (size_t)((ibase + (mlB >> 6)) * NG + jbase + (mlB & 63));
        #pragma unroll
        for (int nt = 0; nt < 4; nt++) {
            const int c = cbase + n0 + nt * 8 + (lane & 3) * 2;
            const float* a = acc[mt][nt];
            if (c < NCLS) {
                const float Cc = d_C[c];
                out[nA * NCLS + c] = a[0] * OSCALE + Cc;
                out[nB * NCLS + c] = a[2] * OSCALE + Cc;
            }
            if (c + 1 < NCLS) {
                const float Cc = d_C[c + 1];
                out[nA * NCLS + c + 1] = a[1] * OSCALE + Cc;
                out[nB * NCLS + c + 1] = a[3] * OSCALE + Cc;
            }
        }
    }
}

// ---------------------------------------------------------------------------
extern "C" void kernel_launch(void* const* d_in, const int* in_sizes, int n_in,
                              void* d_out, int out_size)
{
    const float* probe   = (const float*)d_in[0];
    const float* gallery = (const float*)d_in[1];
    const float* gamma   = (const float*)d_in[2];
    const float* beta    = (const float*)d_in[3];
    const float* W       = (const float*)d_in[4];
    const float* b       = (const float*)d_in[5];
    float* out = (float*)d_out;

    static bool attr_set = false;
    if (!attr_set) {
        cudaFuncSetAttribute(gemm_kernel,
                             cudaFuncAttributeMaxDynamicSharedMemorySize,
                             SMEM_TOTAL);
        attr_set = true;
    }

    stats_kernel<<<FEAT / 16, 256>>>(probe, gallery, gamma, beta);
    build_kernel<<<NROWS / 16, 256>>>(probe, gallery);
    prep_kernel<<<NCLSP, 256>>>(W, b);
    dim3 grid(NCLSP / TNC, NROWS / TM);   // (6, 128)
    gemm_kernel<<<grid, 512, SMEM_TOTAL>>>(out);
}

// round 14
// speedup vs baseline: 1.2055x; 1.2055x over previous
#include <cuda_runtime.h>
#include <cuda_fp16.h>
#include <cstdint>
#include <cstring>

#define FEAT 2048
#define NCLS 751
#define NCLSP 768          // padded classes (6 tiles of 128)
#define NP   64
#define NG   256
#define NROWS (NP * NG)    // 16384
#define EPSV 1e-5f
#define WSCALE 512.0f
#define OSCALE (1.0f / 512.0f)

// GEMM tiling
#define TM   128
#define TNC  128
#define KT   64
#define KITERS (FEAT / KT) // 32

// SMEM: per stage: A 16K | B 16K = 32K; 3 stages + 1K align pad
#define STAGE_BYTES 32768
#define NSTAGE 3
#define SMEM_TOTAL (NSTAGE * STAGE_BYTES + 1024)

// --------------------------- device scratch --------------------------------
__device__ float d_scale[FEAT];
__device__ float d_shift[FEAT];
__device__ float d_C[NCLSP];
__device__ uint4 d_Wp16[NCLSP * (FEAT / 8)];   // fp16 W'*512
__device__ uint4 d_A16[NROWS * (FEAT / 8)];    // fp16 d=(p-g)^2, 64MB

// --------------------------- helpers ----------------------------------------
__device__ __forceinline__ uint32_t smem_u32(const void* p) {
    uint32_t a;
    asm("{ .reg .u64 t; cvta.to.shared.u64 t, %1; cvt.u32.u64 %0, t; }"
        : "=r"(a) : "l"(p));
    return a;
}
__device__ __forceinline__ void ldsm4(uint32_t* r, uint32_t addr) {
    asm volatile("ldmatrix.sync.aligned.m8n8.x4.shared.b16 {%0,%1,%2,%3}, [%4];"
                 : "=r"(r[0]), "=r"(r[1]), "=r"(r[2]), "=r"(r[3]) : "r"(addr));
}
__device__ __forceinline__ void mma16816(float* c, const uint32_t* a,
                                         const uint32_t* b) {
    asm volatile(
        "mma.sync.aligned.m16n8k16.row.col.f32.f16.f16.f32 "
        "{%0,%1,%2,%3}, {%4,%5,%6,%7}, {%8,%9}, {%0,%1,%2,%3};"
        : "+f"(c[0]), "+f"(c[1]), "+f"(c[2]), "+f"(c[3])
        : "r"(a[0]), "r"(a[1]), "r"(a[2]), "r"(a[3]), "r"(b[0]), "r"(b[1]));
}
__device__ __forceinline__ uint32_t pack16(float v0, float v1) {
    __half2 h = __float22half2_rn(make_float2(v0, v1));
    uint32_t u; memcpy(&u, &h, 4); return u;
}
__device__ __forceinline__ void cp16(uint32_t dst, const void* src) {
    asm volatile("cp.async.cg.shared.global [%0], [%1], 16;"
                 :: "r"(dst), "l"(src) : "memory");
}
__device__ __forceinline__ void cp_commit() {
    asm volatile("cp.async.commit_group;" ::: "memory");
}
__device__ __forceinline__ void cp_wait1() {
    asm volatile("cp.async.wait_group 1;" ::: "memory");
}

// ---------------------------------------------------------------------------
// Fused Stage A: blocks [0,128) compute exact batch stats from per-feature
// moments; blocks [128, 128+NROWS) materialize A = (p-g)^2 as fp16.
// The two halves are mutually independent (build does not read stats output),
// so fusing them overlaps stats' latency-bound work with build's
// bandwidth-bound work and removes one launch gap.
// ---------------------------------------------------------------------------
__global__ __launch_bounds__(256)
void stats_build_kernel(const float* __restrict__ probe,
                        const float* __restrict__ gallery,
                        const float* __restrict__ gamma,
                        const float* __restrict__ beta)
{
    if (blockIdx.x < 128) {
        // ---- stats: thread = (feature-in-16, row-slice-of-16) ----
        const int tx = threadIdx.x & 15;
        const int ty = threadIdx.x >> 4;
        const int f  = blockIdx.x * 16 + tx;

        float p1 = 0, p2 = 0, p3 = 0, p4 = 0;
        #pragma unroll
        for (int i = ty * 4; i < ty * 4 + 4; i++) {
            float x = probe[i * FEAT + f];
            float x2 = x * x;
            p1 += x; p2 += x2; p3 += x2 * x; p4 += x2 * x2;
        }
        float g1 = 0, g2 = 0, g3 = 0, g4 = 0;
        #pragma unroll
        for (int j = ty * 16; j < ty * 16 + 16; j++) {
            float x = gallery[j * FEAT + f];
            float x2 = x * x;
            g1 += x; g2 += x2; g3 += x2 * x; g4 += x2 * x2;
        }

        __shared__ float red[8][16][16];
        red[0][ty][tx] = p1; red[1][ty][tx] = p2;
        red[2][ty][tx] = p3; red[3][ty][tx] = p4;
        red[4][ty][tx] = g1; red[5][ty][tx] = g2;
        red[6][ty][tx] = g3; red[7][ty][tx] = g4;
        __syncthreads();
        if (ty != 0) return;

        float m[8];
        #pragma unroll
        for (int q = 0; q < 8; q++) {
            float s = 0.f;
            #pragma unroll
            for (int t = 0; t < 16; t++) s += red[q][t][tx];
            m[q] = s;
        }
        p1 = m[0] * (1.f/NP); p2 = m[1] * (1.f/NP);
        p3 = m[2] * (1.f/NP); p4 = m[3] * (1.f/NP);
        g1 = m[4] * (1.f/NG); g2 = m[5] * (1.f/NG);
        g3 = m[6] * (1.f/NG); g4 = m[7] * (1.f/NG);

        float mean = p2 - 2.f * p1 * g1 + g2;
        float ed2  = p4 - 4.f * p3 * g1 + 6.f * p2 * g2 - 4.f * p1 * g3 + g4;
        float var  = ed2 - mean * mean;
        float s    = gamma[f] * rsqrtf(var + EPSV);
        d_scale[f] = s;
        d_shift[f] = beta[f] - mean * s;
    } else {
        // ---- build: one output row per block ----
        const int n = blockIdx.x - 128;
        const int t = threadIdx.x;
        const int i = n >> 8;
        const int j = n & 255;
        const float4* pp = (const float4*)(probe   + (size_t)i * FEAT) + t * 2;
        const float4* gp = (const float4*)(gallery + (size_t)j * FEAT) + t * 2;
        const float4 pa = pp[0], pb = pp[1], ga = gp[0], gb = gp[1];
        float v0 = pa.x - ga.x; v0 *= v0;
        float v1 = pa.y - ga.y; v1 *= v1;
        float v2 = pa.z - ga.z; v2 *= v2;
        float v3 = pa.w - ga.w; v3 *= v3;
        float v4 = pb.x - gb.x; v4 *= v4;
        float v5 = pb.y - gb.y; v5 *= v5;
        float v6 = pb.z - gb.z; v6 *= v6;
        float v7 = pb.w - gb.w; v7 *= v7;
        d_A16[(size_t)n * 256 + t] = make_uint4(pack16(v0, v1), pack16(v2, v3),
                                                pack16(v4, v5), pack16(v6, v7));
    }
}

// ---------------------------------------------------------------------------
// Stage B: W'[c] = W[c]*scale*512 -> fp16 ; C[c] = b[c] + shift . W[c]
// ---------------------------------------------------------------------------
__global__ void prep_kernel(const float* __restrict__ W,
                            const float* __restrict__ b)
{
    int c = blockIdx.x;
    int t = threadIdx.x;
    if (c >= NCLS) {
        d_Wp16[c * 256 + t] = make_uint4(0, 0, 0, 0);
        if (t == 0) d_C[c] = 0.f;
        return;
    }
    int f0 = t * 8;
    const float4* wp = (const float4*)(W + (size_t)c * FEAT + f0);
    const float4* sp = (const float4*)(d_scale + f0);
    const float4* hp = (const float4*)(d_shift + f0);
    float4 w0 = wp[0], w1 = wp[1];
    float4 s0 = sp[0], s1 = sp[1];
    float4 h0 = hp[0], h1 = hp[1];

    float v0 = w0.x * s0.x * WSCALE, v1 = w0.y * s0.y * WSCALE;
    float v2 = w0.z * s0.z * WSCALE, v3 = w0.w * s0.w * WSCALE;
    float v4 = w1.x * s1.x * WSCALE, v5 = w1.y * s1.y * WSCALE;
    float v6 = w1.z * s1.z * WSCALE, v7 = w1.w * s1.w * WSCALE;
    d_Wp16[c * 256 + t] = make_uint4(pack16(v0, v1), pack16(v2, v3),
                                     pack16(v4, v5), pack16(v6, v7));

    float acc = w0.x*h0.x + w0.y*h0.y + w0.z*h0.z + w0.w*h0.w
              + w1.x*h1.x + w1.y*h1.y + w1.z*h1.z + w1.w*h1.w;
    #pragma unroll
    for (int o = 16; o > 0; o >>= 1)
        acc += __shfl_down_sync(0xFFFFFFFFu, acc, o);
    __shared__ float red[8];
    if ((t & 31) == 0) red[t >> 5] = acc;
    __syncthreads();
    if (t == 0) {
        float s = 0.f;
        #pragma unroll
        for (int w = 0; w < 8; w++) s += red[w];
        d_C[c] = b[c] + s;
    }
}

// ---------------------------------------------------------------------------
// Stage C: pure fp16 mma.sync GEMM (R10 configuration — best measured).
// 512 threads, 16 warps, 32x32 warp tile, 3-stage cp.async pipeline,
// fully unrolled k-loop, batched ldsm per kk, 2 CTAs/SM.
// ---------------------------------------------------------------------------
__global__ __launch_bounds__(512, 2)
void gemm_kernel(float* __restrict__ out)
{
    extern __shared__ char smem_raw[];
    char* smem = (char*)(((uintptr_t)smem_raw + 1023) & ~(uintptr_t)1023);
    const uint32_t sbase = smem_u32(smem);

    const int tid  = threadIdx.x;
    const int wid  = tid >> 5;            // 0..15
    const int lane = tid & 31;

    const int by    = blockIdx.y;
    const int ibase = (by >> 2) * 2;
    const int jbase = (by & 3) * 64;
    const int cbase = blockIdx.x * TNC;

    // ---- staging mapping: thread -> (tile row r, k-chunk h) ----
    const int r = tid >> 2;               // 0..127
    const int h = tid & 3;                // 16B chunk 0..3 (and +4)

    const int nrow = (ibase + (r >> 6)) * NG + jbase + (r & 63);
    const uint4* aRow = d_A16  + (size_t)nrow * 256 + h;
    const uint4* wRow = d_Wp16 + (size_t)(cbase + r) * 256 + h;

    uint32_t swzA0, swzA1;
    {
        const uint32_t o0 = (uint32_t)(r * 128 + h * 16);
        const uint32_t o1 = o0 + 64;
        swzA0 = o0 ^ ((o0 >> 3) & 0x70u);
        swzA1 = o1 ^ ((o1 >> 3) & 0x70u);
    }

    // ---- mma mapping: warp grid 4(m) x 4(n); warp tile 32x32 ----
    const int m0 = (wid >> 2) * 32;
    const int n0 = (wid & 3) * 32;
    const int xr = (lane & 7) * 16;
    const int g  = lane >> 3;             // ldsm4 lane group 0..3

    uint32_t arow[2], akb[4], brow4[2], bkb4[4];
    #pragma unroll
    for (int mt = 0; mt < 2; mt++)
        arow[mt] = (uint32_t)((m0 + mt * 16 + (lane & 15)) * 128);
    #pragma unroll
    for (int p = 0; p < 2; p++)
        brow4[p] = (uint32_t)(16384 +
                   (n0 + (2 * p + (g >> 1)) * 8 + (lane & 7)) * 128);
    #pragma unroll
    for (int kk = 0; kk < 4; kk++) {
        akb[kk]  = (uint32_t)((kk * 32 + (lane >> 4) * 16) ^ xr);
        bkb4[kk] = (uint32_t)((kk * 32 + (g & 1) * 16) ^ xr);
    }

    float acc[2][4][4];
    #pragma unroll
    for (int mt = 0; mt < 2; mt++)
        #pragma unroll
        for (int nt = 0; nt < 4; nt++)
            #pragma unroll
            for (int q = 0; q < 4; q++) acc[mt][nt][q] = 0.f;

    // ---- prologue: stages 0 and 1 ----
    #pragma unroll
    for (int s = 0; s < 2; s++) {
        const uint32_t ad = sbase + s * STAGE_BYTES;
        const uint32_t bd = ad + 16384;
        const uint4* ap = aRow + s * 8;
        const uint4* wp = wRow + s * 8;
        cp16(ad + swzA0, ap);
        cp16(ad + swzA1, ap + 4);
        cp16(bd + swzA0, wp);
        cp16(bd + swzA1, wp + 4);
        cp_commit();
    }

    // ---- fully unrolled main loop ----
    #pragma unroll
    for (int kt = 0; kt < KITERS; kt++) {
        const int buf  = kt % NSTAGE;
        const int nbuf = (kt + 2) % NSTAGE;

        cp_wait1();                   // stage kt resident
        __syncthreads();

        if (kt + 2 < KITERS) {
            const uint32_t ad = sbase + nbuf * STAGE_BYTES;
            const uint32_t bd = ad + 16384;
            const uint4* ap = aRow + (kt + 2) * 8;
            const uint4* wp = wRow + (kt + 2) * 8;
            cp16(ad + swzA0, ap);
            cp16(ad + swzA1, ap + 4);
            cp16(bd + swzA0, wp);
            cp16(bd + swzA1, wp + 4);
        }
        cp_commit();

        const uint32_t sb = sbase + buf * STAGE_BYTES;
        #pragma unroll
        for (int kk = 0; kk < 4; kk++) {
            uint32_t bfa[4], bfb[4], ah0[4], ah1[4];
            ldsm4(bfa, sb + brow4[0] + bkb4[kk]);   // nt 0,1
            ldsm4(bfb, sb + brow4[1] + bkb4[kk]);   // nt 2,3
            ldsm4(ah0, sb + arow[0]  + akb[kk]);    // mt 0
            ldsm4(ah1, sb + arow[1]  + akb[kk]);    // mt 1
            mma16816(acc[0][0], ah0, &bfa[0]);
            mma16816(acc[0][1], ah0, &bfa[2]);
            mma16816(acc[0][2], ah0, &bfb[0]);
            mma16816(acc[0][3], ah0, &bfb[2]);
            mma16816(acc[1][0], ah1, &bfa[0]);
            mma16816(acc[1][1], ah1, &bfa[2]);
            mma16816(acc[1][2], ah1, &bfb[0]);
            mma16816(acc[1][3], ah1, &bfb[2]);
        }
    }

    // ---- epilogue ----
    #pragma unroll
    for (int mt = 0; mt < 2; mt++) {
        const int mlA = m0 + mt * 16 + (lane >> 2);
        const int mlB = mlA + 8;
        const size_t nA = (size_t)((ibase + (mlA >> 6)) * NG + jbase + (mlA & 63));
        const size_t nB = (size_t)((ibase + (mlB >> 6)) * NG + jbase + (mlB & 63));
        #pragma unroll
        for (int nt = 0; nt < 4; nt++) {
            const int c = cbase + n0 + nt * 8 + (lane & 3) * 2;
            const float* a = acc[mt][nt];
            if (c < NCLS) {
                const float Cc = d_C[c];
                out[nA * NCLS + c] = a[0] * OSCALE + Cc;
                out[nB * NCLS + c] = a[2] * OSCALE + Cc;
            }
            if (c + 1 < NCLS) {
                const float Cc = d_C[c + 1];
                out[nA * NCLS + c + 1] = a[1] * OSCALE + Cc;
                out[nB * NCLS + c + 1] = a[3] * OSCALE + Cc;
            }
        }
    }
}

// ---------------------------------------------------------------------------
extern "C" void kernel_launch(void* const* d_in, const int* in_sizes, int n_in,
                              void* d_out, int out_size)
{
    const float* probe   = (const float*)d_in[0];
    const float* gallery = (const float*)d_in[1];
    const float* gamma   = (const float*)d_in[2];
    const float* beta    = (const float*)d_in[3];
    const float* W       = (const float*)d_in[4];
    const float* b       = (const float*)d_in[5];
    float* out = (float*)d_out;

    static bool attr_set = false;
    if (!attr_set) {
        cudaFuncSetAttribute(gemm_kernel,
                             cudaFuncAttributeMaxDynamicSharedMemorySize,
                             SMEM_TOTAL);
        attr_set = true;
    }

    stats_build_kernel<<<128 + NROWS, 256>>>(probe, gallery, gamma, beta);
    prep_kernel<<<NCLSP, 256>>>(W, b);
    dim3 grid(NCLSP / TNC, NROWS / TM);   // (6, 128)
    gemm_kernel<<<grid, 512, SMEM_TOTAL>>>(out);
}

// round 15
// speedup vs baseline: 1.2383x; 1.0273x over previous
#include <cuda_runtime.h>
#include <cuda_fp16.h>
#include <cstdint>
#include <cstring>

#define FEAT 2048
#define NCLS 751
#define NCLSP 768          // padded classes (6 tiles of 128)
#define NP   64
#define NG   256
#define NROWS (NP * NG)    // 16384
#define EPSV 1e-5f
#define WSCALE 512.0f
#define OSCALE (1.0f / 512.0f)

// GEMM tiling
#define TM   128
#define TNC  128
#define KT   64
#define KITERS (FEAT / KT) // 32

// SMEM: per stage: A 16K | B 16K = 32K; 3 stages + 1K align pad
#define STAGE_BYTES 32768
#define NSTAGE 3
#define SMEM_TOTAL (NSTAGE * STAGE_BYTES + 1024)

// --------------------------- device scratch --------------------------------
__device__ float d_scale[FEAT];
__device__ float d_shift[FEAT];
__device__ float d_C[NCLSP];
__device__ uint4 d_Wp16[NCLSP * (FEAT / 8)];   // fp16 W'*512
__device__ uint4 d_A16[NROWS * (FEAT / 8)];    // fp16 d=(p-g)^2, 64MB

// --------------------------- helpers ----------------------------------------
__device__ __forceinline__ uint32_t smem_u32(const void* p) {
    uint32_t a;
    asm("{ .reg .u64 t; cvta.to.shared.u64 t, %1; cvt.u32.u64 %0, t; }"
        : "=r"(a) : "l"(p));
    return a;
}
__device__ __forceinline__ void ldsm4(uint32_t* r, uint32_t addr) {
    asm volatile("ldmatrix.sync.aligned.m8n8.x4.shared.b16 {%0,%1,%2,%3}, [%4];"
                 : "=r"(r[0]), "=r"(r[1]), "=r"(r[2]), "=r"(r[3]) : "r"(addr));
}
__device__ __forceinline__ void mma16816(float* c, const uint32_t* a,
                                         const uint32_t* b) {
    asm volatile(
        "mma.sync.aligned.m16n8k16.row.col.f32.f16.f16.f32 "
        "{%0,%1,%2,%3}, {%4,%5,%6,%7}, {%8,%9}, {%0,%1,%2,%3};"
        : "+f"(c[0]), "+f"(c[1]), "+f"(c[2]), "+f"(c[3])
        : "r"(a[0]), "r"(a[1]), "r"(a[2]), "r"(a[3]), "r"(b[0]), "r"(b[1]));
}
__device__ __forceinline__ uint32_t pack16(float v0, float v1) {
    __half2 h = __float22half2_rn(make_float2(v0, v1));
    uint32_t u; memcpy(&u, &h, 4); return u;
}
__device__ __forceinline__ void cp16(uint32_t dst, const void* src) {
    asm volatile("cp.async.cg.shared.global [%0], [%1], 16;"
                 :: "r"(dst), "l"(src) : "memory");
}
__device__ __forceinline__ void cp_commit() {
    asm volatile("cp.async.commit_group;" ::: "memory");
}
__device__ __forceinline__ void cp_wait1() {
    asm volatile("cp.async.wait_group 1;" ::: "memory");
}

// ---------------------------------------------------------------------------
// Fused Stage A: blocks [0,128) compute exact batch stats; blocks
// [128, 128+2048) materialize A = (p-g)^2 as fp16 with probe-register reuse:
// each build block handles one probe row x 8 gallery rows, loading the probe
// slice ONCE into registers (LSU ops per 16B output: 5 -> 3.25).
// ---------------------------------------------------------------------------
__global__ __launch_bounds__(256)
void stats_build_kernel(const float* __restrict__ probe,
                        const float* __restrict__ gallery,
                        const float* __restrict__ gamma,
                        const float* __restrict__ beta)
{
    if (blockIdx.x < 128) {
        // ---- stats: thread = (feature-in-16, row-slice-of-16) ----
        const int tx = threadIdx.x & 15;
        const int ty = threadIdx.x >> 4;
        const int f  = blockIdx.x * 16 + tx;

        float p1 = 0, p2 = 0, p3 = 0, p4 = 0;
        #pragma unroll
        for (int i = ty * 4; i < ty * 4 + 4; i++) {
            float x = probe[i * FEAT + f];
            float x2 = x * x;
            p1 += x; p2 += x2; p3 += x2 * x; p4 += x2 * x2;
        }
        float g1 = 0, g2 = 0, g3 = 0, g4 = 0;
        #pragma unroll
        for (int j = ty * 16; j < ty * 16 + 16; j++) {
            float x = gallery[j * FEAT + f];
            float x2 = x * x;
            g1 += x; g2 += x2; g3 += x2 * x; g4 += x2 * x2;
        }

        __shared__ float red[8][16][16];
        red[0][ty][tx] = p1; red[1][ty][tx] = p2;
        red[2][ty][tx] = p3; red[3][ty][tx] = p4;
        red[4][ty][tx] = g1; red[5][ty][tx] = g2;
        red[6][ty][tx] = g3; red[7][ty][tx] = g4;
        __syncthreads();
        if (ty != 0) return;

        float m[8];
        #pragma unroll
        for (int q = 0; q < 8; q++) {
            float s = 0.f;
            #pragma unroll
            for (int t = 0; t < 16; t++) s += red[q][t][tx];
            m[q] = s;
        }
        p1 = m[0] * (1.f/NP); p2 = m[1] * (1.f/NP);
        p3 = m[2] * (1.f/NP); p4 = m[3] * (1.f/NP);
        g1 = m[4] * (1.f/NG); g2 = m[5] * (1.f/NG);
        g3 = m[6] * (1.f/NG); g4 = m[7] * (1.f/NG);

        float mean = p2 - 2.f * p1 * g1 + g2;
        float ed2  = p4 - 4.f * p3 * g1 + 6.f * p2 * g2 - 4.f * p1 * g3 + g4;
        float var  = ed2 - mean * mean;
        float s    = gamma[f] * rsqrtf(var + EPSV);
        d_scale[f] = s;
        d_shift[f] = beta[f] - mean * s;
    } else {
        // ---- build: one probe row x 8 gallery rows per block ----
        const int bb = blockIdx.x - 128;    // 0..2047
        const int i  = bb >> 5;             // probe row
        const int j0 = (bb & 31) * 8;       // gallery group base
        const int t  = threadIdx.x;

        const float4* pp = (const float4*)(probe + (size_t)i * FEAT) + t * 2;
        const float4 pa = pp[0], pb = pp[1];
        uint4* dst = d_A16 + (size_t)(i * NG + j0) * 256 + t;

        #pragma unroll 2
        for (int jj = 0; jj < 8; jj++) {
            const float4* gp =
                (const float4*)(gallery + (size_t)(j0 + jj) * FEAT) + t * 2;
            const float4 ga = gp[0], gb = gp[1];
            float v0 = pa.x - ga.x; v0 *= v0;
            float v1 = pa.y - ga.y; v1 *= v1;
            float v2 = pa.z - ga.z; v2 *= v2;
            float v3 = pa.w - ga.w; v3 *= v3;
            float v4 = pb.x - gb.x; v4 *= v4;
            float v5 = pb.y - gb.y; v5 *= v5;
            float v6 = pb.z - gb.z; v6 *= v6;
            float v7 = pb.w - gb.w; v7 *= v7;
            dst[(size_t)jj * 256] = make_uint4(pack16(v0, v1), pack16(v2, v3),
                                               pack16(v4, v5), pack16(v6, v7));
        }
    }
}

// ---------------------------------------------------------------------------
// Stage B: W'[c] = W[c]*scale*512 -> fp16 ; C[c] = b[c] + shift . W[c]
// ---------------------------------------------------------------------------
__global__ void prep_kernel(const float* __restrict__ W,
                            const float* __restrict__ b)
{
    int c = blockIdx.x;
    int t = threadIdx.x;
    if (c >= NCLS) {
        d_Wp16[c * 256 + t] = make_uint4(0, 0, 0, 0);
        if (t == 0) d_C[c] = 0.f;
        return;
    }
    int f0 = t * 8;
    const float4* wp = (const float4*)(W + (size_t)c * FEAT + f0);
    const float4* sp = (const float4*)(d_scale + f0);
    const float4* hp = (const float4*)(d_shift + f0);
    float4 w0 = wp[0], w1 = wp[1];
    float4 s0 = sp[0], s1 = sp[1];
    float4 h0 = hp[0], h1 = hp[1];

    float v0 = w0.x * s0.x * WSCALE, v1 = w0.y * s0.y * WSCALE;
    float v2 = w0.z * s0.z * WSCALE, v3 = w0.w * s0.w * WSCALE;
    float v4 = w1.x * s1.x * WSCALE, v5 = w1.y * s1.y * WSCALE;
    float v6 = w1.z * s1.z * WSCALE, v7 = w1.w * s1.w * WSCALE;
    d_Wp16[c * 256 + t] = make_uint4(pack16(v0, v1), pack16(v2, v3),
                                     pack16(v4, v5), pack16(v6, v7));

    float acc = w0.x*h0.x + w0.y*h0.y + w0.z*h0.z + w0.w*h0.w
              + w1.x*h1.x + w1.y*h1.y + w1.z*h1.z + w1.w*h1.w;
    #pragma unroll
    for (int o = 16; o > 0; o >>= 1)
        acc += __shfl_down_sync(0xFFFFFFFFu, acc, o);
    __shared__ float red[8];
    if ((t & 31) == 0) red[t >> 5] = acc;
    __syncthreads();
    if (t == 0) {
        float s = 0.f;
        #pragma unroll
        for (int w = 0; w < 8; w++) s += red[w];
        d_C[c] = b[c] + s;
    }
}

// ---------------------------------------------------------------------------
// Stage C: pure fp16 mma.sync GEMM (R10/R14 configuration — best measured).
// 512 threads, 16 warps, 32x32 warp tile, 3-stage cp.async pipeline,
// fully unrolled k-loop, batched ldsm per kk, 2 CTAs/SM.
// ---------------------------------------------------------------------------
__global__ __launch_bounds__(512, 2)
void gemm_kernel(float* __restrict__ out)
{
    extern __shared__ char smem_raw[];
    char* smem = (char*)(((uintptr_t)smem_raw + 1023) & ~(uintptr_t)1023);
    const uint32_t sbase = smem_u32(smem);

    const int tid  = threadIdx.x;
    const int wid  = tid >> 5;            // 0..15
    const int lane = tid & 31;

    const int by    = blockIdx.y;
    const int ibase = (by >> 2) * 2;
    const int jbase = (by & 3) * 64;
    const int cbase = blockIdx.x * TNC;

    // ---- staging mapping: thread -> (tile row r, k-chunk h) ----
    const int r = tid >> 2;               // 0..127
    const int h = tid & 3;                // 16B chunk 0..3 (and +4)

    const int nrow = (ibase + (r >> 6)) * NG + jbase + (r & 63);
    const uint4* aRow = d_A16  + (size_t)nrow * 256 + h;
    const uint4* wRow = d_Wp16 + (size_t)(cbase + r) * 256 + h;

    uint32_t swzA0, swzA1;
    {
        const uint32_t o0 = (uint32_t)(r * 128 + h * 16);
        const uint32_t o1 = o0 + 64;
        swzA0 = o0 ^ ((o0 >> 3) & 0x70u);
        swzA1 = o1 ^ ((o1 >> 3) & 0x70u);
    }

    // ---- mma mapping: warp grid 4(m) x 4(n); warp tile 32x32 ----
    const int m0 = (wid >> 2) * 32;
    const int n0 = (wid & 3) * 32;
    const int xr = (lane & 7) * 16;
    const int g  = lane >> 3;             // ldsm4 lane group 0..3

    uint32_t arow[2], akb[4], brow4[2], bkb4[4];
    #pragma unroll
    for (int mt = 0; mt < 2; mt++)
        arow[mt] = (uint32_t)((m0 + mt * 16 + (lane & 15)) * 128);
    #pragma unroll
    for (int p = 0; p < 2; p++)
        brow4[p] = (uint32_t)(16384 +
                   (n0 + (2 * p + (g >> 1)) * 8 + (lane & 7)) * 128);
    #pragma unroll
    for (int kk = 0; kk < 4; kk++) {
        akb[kk]  = (uint32_t)((kk * 32 + (lane >> 4) * 16) ^ xr);
        bkb4[kk] = (uint32_t)((kk * 32 + (g & 1) * 16) ^ xr);
    }

    float acc[2][4][4];
    #pragma unroll
    for (int mt = 0; mt < 2; mt++)
        #pragma unroll
        for (int nt = 0; nt < 4; nt++)
            #pragma unroll
            for (int q = 0; q < 4; q++) acc[mt][nt][q] = 0.f;

    // ---- prologue: stages 0 and 1 ----
    #pragma unroll
    for (int s = 0; s < 2; s++) {
        const uint32_t ad = sbase + s * STAGE_BYTES;
        const uint32_t bd = ad + 16384;
        const uint4* ap = aRow + s * 8;
        const uint4* wp = wRow + s * 8;
        cp16(ad + swzA0, ap);
        cp16(ad + swzA1, ap + 4);
        cp16(bd + swzA0, wp);
        cp16(bd + swzA1, wp + 4);
        cp_commit();
    }

    // ---- fully unrolled main loop ----
    #pragma unroll
    for (int kt = 0; kt < KITERS; kt++) {
        const int buf  = kt % NSTAGE;
        const int nbuf = (kt + 2) % NSTAGE;

        cp_wait1();                   // stage kt resident
        __syncthreads();

        if (kt + 2 < KITERS) {
            const uint32_t ad = sbase + nbuf * STAGE_BYTES;
            const uint32_t bd = ad + 16384;
            const uint4* ap = aRow + (kt + 2) * 8;
            const uint4* wp = wRow + (kt + 2) * 8;
            cp16(ad + swzA0, ap);
            cp16(ad + swzA1, ap + 4);
            cp16(bd + swzA0, wp);
            cp16(bd + swzA1, wp + 4);
        }
        cp_commit();

        const uint32_t sb = sbase + buf * STAGE_BYTES;
        #pragma unroll
        for (int kk = 0; kk < 4; kk++) {
            uint32_t bfa[4], bfb[4], ah0[4], ah1[4];
            ldsm4(bfa, sb + brow4[0] + bkb4[kk]);   // nt 0,1
            ldsm4(bfb, sb + brow4[1] + bkb4[kk]);   // nt 2,3
            ldsm4(ah0, sb + arow[0]  + akb[kk]);    // mt 0
            ldsm4(ah1, sb + arow[1]  + akb[kk]);    // mt 1
            mma16816(acc[0][0], ah0, &bfa[0]);
            mma16816(acc[0][1], ah0, &bfa[2]);
            mma16816(acc[0][2], ah0, &bfb[0]);
            mma16816(acc[0][3], ah0, &bfb[2]);
            mma16816(acc[1][0], ah1, &bfa[0]);
            mma16816(acc[1][1], ah1, &bfa[2]);
            mma16816(acc[1][2], ah1, &bfb[0]);
            mma16816(acc[1][3], ah1, &bfb[2]);
        }
    }

    // ---- epilogue ----
    #pragma unroll
    for (int mt = 0; mt < 2; mt++) {
        const int mlA = m0 + mt * 16 + (lane >> 2);
        const int mlB = mlA + 8;
        const size_t nA = (size_t)((ibase + (mlA >> 6)) * NG + jbase + (mlA & 63));
        const size_t nB = (size_t)((ibase + (mlB >> 6)) * NG + jbase + (mlB & 63));
        #pragma unroll
        for (int nt = 0; nt < 4; nt++) {
            const int c = cbase + n0 + nt * 8 + (lane & 3) * 2;
            const float* a = acc[mt][nt];
            if (c < NCLS) {
                const float Cc = d_C[c];
                out[nA * NCLS + c] = a[0] * OSCALE + Cc;
                out[nB * NCLS + c] = a[2] * OSCALE + Cc;
            }
            if (c + 1 < NCLS) {
                const float Cc = d_C[c + 1];
                out[nA * NCLS + c + 1] = a[1] * OSCALE + Cc;
                out[nB * NCLS + c + 1] = a[3] * OSCALE + Cc;
            }
        }
    }
}

// ---------------------------------------------------------------------------
extern "C" void kernel_launch(void* const* d_in, const int* in_sizes, int n_in,
                              void* d_out, int out_size)
{
    const float* probe   = (const float*)d_in[0];
    const float* gallery = (const float*)d_in[1];
    const float* gamma   = (const float*)d_in[2];
    const float* beta    = (const float*)d_in[3];
    const float* W       = (const float*)d_in[4];
    const float* b       = (const float*)d_in[5];
    float* out = (float*)d_out;

    static bool attr_set = false;
    if (!attr_set) {
        cudaFuncSetAttribute(gemm_kernel,
                             cudaFuncAttributeMaxDynamicSharedMemorySize,
                             SMEM_TOTAL);
        attr_set = true;
    }

    stats_build_kernel<<<128 + 2048, 256>>>(probe, gallery, gamma, beta);
    prep_kernel<<<NCLSP, 256>>>(W, b);
    dim3 grid(NCLSP / TNC, NROWS / TM);   // (6, 128)
    gemm_kernel<<<grid, 512, SMEM_TOTAL>>>(out);
}

// round 16
// speedup vs baseline: 1.2610x; 1.0183x over previous
#include <cuda_runtime.h>
#include <cuda_fp16.h>
#include <cstdint>
#include <cstring>

#define FEAT 2048
#define NCLS 751
#define NCLSP 768          // padded classes (6 tiles of 128)
#define NP   64
#define NG   256
#define NROWS (NP * NG)    // 16384
#define EPSV 1e-5f
#define WSCALE 512.0f
#define OSCALE (1.0f / 512.0f)

// GEMM tiling
#define TM   128
#define TNC  128
#define KT   64
#define KITERS (FEAT / KT) // 32

// SMEM: per stage: A 16K | B 16K = 32K; 3 stages + 1K align pad
#define STAGE_BYTES 32768
#define NSTAGE 3
#define SMEM_TOTAL (NSTAGE * STAGE_BYTES + 1024)

// --------------------------- device scratch --------------------------------
__device__ float d_scale[FEAT];
__device__ float d_shift[FEAT];
__device__ float d_C[NCLSP];
__device__ uint4 d_Wp16[NCLSP * (FEAT / 8)];   // fp16 W'*512
__device__ uint4 d_A16[NROWS * (FEAT / 8)];    // fp16 d=(p-g)^2, 64MB

// --------------------------- helpers ----------------------------------------
__device__ __forceinline__ uint32_t smem_u32(const void* p) {
    uint32_t a;
    asm("{ .reg .u64 t; cvta.to.shared.u64 t, %1; cvt.u32.u64 %0, t; }"
        : "=r"(a) : "l"(p));
    return a;
}
__device__ __forceinline__ void ldsm4(uint32_t* r, uint32_t addr) {
    asm volatile("ldmatrix.sync.aligned.m8n8.x4.shared.b16 {%0,%1,%2,%3}, [%4];"
                 : "=r"(r[0]), "=r"(r[1]), "=r"(r[2]), "=r"(r[3]) : "r"(addr));
}
__device__ __forceinline__ void mma16816(float* c, const uint32_t* a,
                                         const uint32_t* b) {
    asm volatile(
        "mma.sync.aligned.m16n8k16.row.col.f32.f16.f16.f32 "
        "{%0,%1,%2,%3}, {%4,%5,%6,%7}, {%8,%9}, {%0,%1,%2,%3};"
        : "+f"(c[0]), "+f"(c[1]), "+f"(c[2]), "+f"(c[3])
        : "r"(a[0]), "r"(a[1]), "r"(a[2]), "r"(a[3]), "r"(b[0]), "r"(b[1]));
}
__device__ __forceinline__ uint32_t pack16(float v0, float v1) {
    __half2 h = __float22half2_rn(make_float2(v0, v1));
    uint32_t u; memcpy(&u, &h, 4); return u;
}
__device__ __forceinline__ void cp16(uint32_t dst, const void* src) {
    asm volatile("cp.async.cg.shared.global [%0], [%1], 16;"
                 :: "r"(dst), "l"(src) : "memory");
}
__device__ __forceinline__ void cp_commit() {
    asm volatile("cp.async.commit_group;" ::: "memory");
}
__device__ __forceinline__ void cp_wait1() {
    asm volatile("cp.async.wait_group 1;" ::: "memory");
}

// ---------------------------------------------------------------------------
// Fused Stage A: blocks [0,128) compute exact batch stats; blocks
// [128, 128+1024) materialize A = (p-g)^2 as fp16.
// Each build block: 2 probe rows x 8 gallery rows; probe slices in registers,
// each gallery slice loaded ONCE and used for both probes.
// LSU ops per 16B output: 3.25 -> 2.0.
// ---------------------------------------------------------------------------
__global__ __launch_bounds__(256)
void stats_build_kernel(const float* __restrict__ probe,
                        const float* __restrict__ gallery,
                        const float* __restrict__ gamma,
                        const float* __restrict__ beta)
{
    if (blockIdx.x < 128) {
        // ---- stats: thread = (feature-in-16, row-slice-of-16) ----
        const int tx = threadIdx.x & 15;
        const int ty = threadIdx.x >> 4;
        const int f  = blockIdx.x * 16 + tx;

        float p1 = 0, p2 = 0, p3 = 0, p4 = 0;
        #pragma unroll
        for (int i = ty * 4; i < ty * 4 + 4; i++) {
            float x = probe[i * FEAT + f];
            float x2 = x * x;
            p1 += x; p2 += x2; p3 += x2 * x; p4 += x2 * x2;
        }
        float g1 = 0, g2 = 0, g3 = 0, g4 = 0;
        #pragma unroll
        for (int j = ty * 16; j < ty * 16 + 16; j++) {
            float x = gallery[j * FEAT + f];
            float x2 = x * x;
            g1 += x; g2 += x2; g3 += x2 * x; g4 += x2 * x2;
        }

        __shared__ float red[8][16][16];
        red[0][ty][tx] = p1; red[1][ty][tx] = p2;
        red[2][ty][tx] = p3; red[3][ty][tx] = p4;
        red[4][ty][tx] = g1; red[5][ty][tx] = g2;
        red[6][ty][tx] = g3; red[7][ty][tx] = g4;
        __syncthreads();
        if (ty != 0) return;

        float m[8];
        #pragma unroll
        for (int q = 0; q < 8; q++) {
            float s = 0.f;
            #pragma unroll
            for (int t = 0; t < 16; t++) s += red[q][t][tx];
            m[q] = s;
        }
        p1 = m[0] * (1.f/NP); p2 = m[1] * (1.f/NP);
        p3 = m[2] * (1.f/NP); p4 = m[3] * (1.f/NP);
        g1 = m[4] * (1.f/NG); g2 = m[5] * (1.f/NG);
        g3 = m[6] * (1.f/NG); g4 = m[7] * (1.f/NG);

        float mean = p2 - 2.f * p1 * g1 + g2;
        float ed2  = p4 - 4.f * p3 * g1 + 6.f * p2 * g2 - 4.f * p1 * g3 + g4;
        float var  = ed2 - mean * mean;
        float s    = gamma[f] * rsqrtf(var + EPSV);
        d_scale[f] = s;
        d_shift[f] = beta[f] - mean * s;
    } else {
        // ---- build: 2 probe rows x 8 gallery rows per block ----
        const int bb = blockIdx.x - 128;    // 0..1023
        const int i0 = (bb >> 5) * 2;       // probe pair base
        const int j0 = (bb & 31) * 8;       // gallery group base
        const int t  = threadIdx.x;

        const float4* pp0 = (const float4*)(probe + (size_t)i0 * FEAT) + t * 2;
        const float4* pp1 = (const float4*)(probe + (size_t)(i0 + 1) * FEAT) + t * 2;
        const float4 pa0 = pp0[0], pb0 = pp0[1];
        const float4 pa1 = pp1[0], pb1 = pp1[1];
        uint4* dst0 = d_A16 + (size_t)(i0 * NG + j0) * 256 + t;
        uint4* dst1 = dst0 + (size_t)NG * 256;

        #pragma unroll 2
        for (int jj = 0; jj < 8; jj++) {
            const float4* gp =
                (const float4*)(gallery + (size_t)(j0 + jj) * FEAT) + t * 2;
            const float4 ga = gp[0], gb = gp[1];
            // probe i0
            float v0 = pa0.x - ga.x; v0 *= v0;
            float v1 = pa0.y - ga.y; v1 *= v1;
            float v2 = pa0.z - ga.z; v2 *= v2;
            float v3 = pa0.w - ga.w; v3 *= v3;
            float v4 = pb0.x - gb.x; v4 *= v4;
            float v5 = pb0.y - gb.y; v5 *= v5;
            float v6 = pb0.z - gb.z; v6 *= v6;
            float v7 = pb0.w - gb.w; v7 *= v7;
            dst0[(size_t)jj * 256] = make_uint4(pack16(v0, v1), pack16(v2, v3),
                                                pack16(v4, v5), pack16(v6, v7));
            // probe i0+1 (same gallery slice)
            float u0 = pa1.x - ga.x; u0 *= u0;
            float u1 = pa1.y - ga.y; u1 *= u1;
            float u2 = pa1.z - ga.z; u2 *= u2;
            float u3 = pa1.w - ga.w; u3 *= u3;
            float u4 = pb1.x - gb.x; u4 *= u4;
            float u5 = pb1.y - gb.y; u5 *= u5;
            float u6 = pb1.z - gb.z; u6 *= u6;
            float u7 = pb1.w - gb.w; u7 *= u7;
            dst1[(size_t)jj * 256] = make_uint4(pack16(u0, u1), pack16(u2, u3),
                                                pack16(u4, u5), pack16(u6, u7));
        }
    }
}

// ---------------------------------------------------------------------------
// Stage B: W'[c] = W[c]*scale*512 -> fp16 ; C[c] = b[c] + shift . W[c]
// ---------------------------------------------------------------------------
__global__ void prep_kernel(const float* __restrict__ W,
                            const float* __restrict__ b)
{
    int c = blockIdx.x;
    int t = threadIdx.x;
    if (c >= NCLS) {
        d_Wp16[c * 256 + t] = make_uint4(0, 0, 0, 0);
        if (t == 0) d_C[c] = 0.f;
        return;
    }
    int f0 = t * 8;
    const float4* wp = (const float4*)(W + (size_t)c * FEAT + f0);
    const float4* sp = (const float4*)(d_scale + f0);
    const float4* hp = (const float4*)(d_shift + f0);
    float4 w0 = wp[0], w1 = wp[1];
    float4 s0 = sp[0], s1 = sp[1];
    float4 h0 = hp[0], h1 = hp[1];

    float v0 = w0.x * s0.x * WSCALE, v1 = w0.y * s0.y * WSCALE;
    float v2 = w0.z * s0.z * WSCALE, v3 = w0.w * s0.w * WSCALE;
    float v4 = w1.x * s1.x * WSCALE, v5 = w1.y * s1.y * WSCALE;
    float v6 = w1.z * s1.z * WSCALE, v7 = w1.w * s1.w * WSCALE;
    d_Wp16[c * 256 + t] = make_uint4(pack16(v0, v1), pack16(v2, v3),
                                     pack16(v4, v5), pack16(v6, v7));

    float acc = w0.x*h0.x + w0.y*h0.y + w0.z*h0.z + w0.w*h0.w
              + w1.x*h1.x + w1.y*h1.y + w1.z*h1.z + w1.w*h1.w;
    #pragma unroll
    for (int o = 16; o > 0; o >>= 1)
        acc += __shfl_down_sync(0xFFFFFFFFu, acc, o);
    __shared__ float red[8];
    if ((t & 31) == 0) red[t >> 5] = acc;
    __syncthreads();
    if (t == 0) {
        float s = 0.f;
        #pragma unroll
        for (int w = 0; w < 8; w++) s += red[w];
        d_C[c] = b[c] + s;
    }
}

// ---------------------------------------------------------------------------
// Stage C: pure fp16 mma.sync GEMM (R10/R14 configuration — best measured).
// 512 threads, 16 warps, 32x32 warp tile, 3-stage cp.async pipeline,
// fully unrolled k-loop, batched ldsm per kk, 2 CTAs/SM.
// ---------------------------------------------------------------------------
__global__ __launch_bounds__(512, 2)
void gemm_kernel(float* __restrict__ out)
{
    extern __shared__ char smem_raw[];
    char* smem = (char*)(((uintptr_t)smem_raw + 1023) & ~(uintptr_t)1023);
    const uint32_t sbase = smem_u32(smem);

    const int tid  = threadIdx.x;
    const int wid  = tid >> 5;            // 0..15
    const int lane = tid & 31;

    const int by    = blockIdx.y;
    const int ibase = (by >> 2) * 2;
    const int jbase = (by & 3) * 64;
    const int cbase = blockIdx.x * TNC;

    // ---- staging mapping: thread -> (tile row r, k-chunk h) ----
    const int r = tid >> 2;               // 0..127
    const int h = tid & 3;                // 16B chunk 0..3 (and +4)

    const int nrow = (ibase + (r >> 6)) * NG + jbase + (r & 63);
    const uint4* aRow = d_A16  + (size_t)nrow * 256 + h;
    const uint4* wRow = d_Wp16 + (size_t)(cbase + r) * 256 + h;

    uint32_t swzA0, swzA1;
    {
        const uint32_t o0 = (uint32_t)(r * 128 + h * 16);
        const uint32_t o1 = o0 + 64;
        swzA0 = o0 ^ ((o0 >> 3) & 0x70u);
        swzA1 = o1 ^ ((o1 >> 3) & 0x70u);
    }

    // ---- mma mapping: warp grid 4(m) x 4(n); warp tile 32x32 ----
    const int m0 = (wid >> 2) * 32;
    const int n0 = (wid & 3) * 32;
    const int xr = (lane & 7) * 16;
    const int g  = lane >> 3;             // ldsm4 lane group 0..3

    uint32_t arow[2], akb[4], brow4[2], bkb4[4];
    #pragma unroll
    for (int mt = 0; mt < 2; mt++)
        arow[mt] = (uint32_t)((m0 + mt * 16 + (lane & 15)) * 128);
    #pragma unroll
    for (int p = 0; p < 2; p++)
        brow4[p] = (uint32_t)(16384 +
                   (n0 + (2 * p + (g >> 1)) * 8 + (lane & 7)) * 128);
    #pragma unroll
    for (int kk = 0; kk < 4; kk++) {
        akb[kk]  = (uint32_t)((kk * 32 + (lane >> 4) * 16) ^ xr);
        bkb4[kk] = (uint32_t)((kk * 32 + (g & 1) * 16) ^ xr);
    }

    float acc[2][4][4];
    #pragma unroll
    for (int mt = 0; mt < 2; mt++)
        #pragma unroll
        for (int nt = 0; nt < 4; nt++)
            #pragma unroll
            for (int q = 0; q < 4; q++) acc[mt][nt][q] = 0.f;

    // ---- prologue: stages 0 and 1 ----
    #pragma unroll
    for (int s = 0; s < 2; s++) {
        const uint32_t ad = sbase + s * STAGE_BYTES;
        const uint32_t bd = ad + 16384;
        const uint4* ap = aRow + s * 8;
        const uint4* wp = wRow + s * 8;
        cp16(ad + swzA0, ap);
        cp16(ad + swzA1, ap + 4);
        cp16(bd + swzA0, wp);
        cp16(bd + swzA1, wp + 4);
        cp_commit();
    }

    // ---- fully unrolled main loop ----
    #pragma unroll
    for (int kt = 0; kt < KITERS; kt++) {
        const int buf  = kt % NSTAGE;
        const int nbuf = (kt + 2) % NSTAGE;

        cp_wait1();                   // stage kt resident
        __syncthreads();

        if (kt + 2 < KITERS) {
            const uint32_t ad = sbase + nbuf * STAGE_BYTES;
            const uint32_t bd = ad + 16384;
            const uint4* ap = aRow + (kt + 2) * 8;
            const uint4* wp = wRow + (kt + 2) * 8;
            cp16(ad + swzA0, ap);
            cp16(ad + swzA1, ap + 4);
            cp16(bd + swzA0, wp);
            cp16(bd + swzA1, wp + 4);
        }
        cp_commit();

        const uint32_t sb = sbase + buf * STAGE_BYTES;
        #pragma unroll
        for (int kk = 0; kk < 4; kk++) {
            uint32_t bfa[4], bfb[4], ah0[4], ah1[4];
            ldsm4(bfa, sb + brow4[0] + bkb4[kk]);   // nt 0,1
            ldsm4(bfb, sb + brow4[1] + bkb4[kk]);   // nt 2,3
            ldsm4(ah0, sb + arow[0]  + akb[kk]);    // mt 0
            ldsm4(ah1, sb + arow[1]  + akb[kk]);    // mt 1
            mma16816(acc[0][0], ah0, &bfa[0]);
            mma16816(acc[0][1], ah0, &bfa[2]);
            mma16816(acc[0][2], ah0, &bfb[0]);
            mma16816(acc[0][3], ah0, &bfb[2]);
            mma16816(acc[1][0], ah1, &bfa[0]);
            mma16816(acc[1][1], ah1, &bfa[2]);
            mma16816(acc[1][2], ah1, &bfb[0]);
            mma16816(acc[1][3], ah1, &bfb[2]);
        }
    }

    // ---- epilogue ----
    #pragma unroll
    for (int mt = 0; mt < 2; mt++) {
        const int mlA = m0 + mt * 16 + (lane >> 2);
        const int mlB = mlA + 8;
        const size_t nA = (size_t)((ibase + (mlA >> 6)) * NG + jbase + (mlA & 63));
        const size_t nB = (size_t)((ibase + (mlB >> 6)) * NG + jbase + (mlB & 63));
        #pragma unroll
        for (int nt = 0; nt < 4; nt++) {
            const int c = cbase + n0 + nt * 8 + (lane & 3) * 2;
            const float* a = acc[mt][nt];
            if (c < NCLS) {
                const float Cc = d_C[c];
                out[nA * NCLS + c] = a[0] * OSCALE + Cc;
                out[nB * NCLS + c] = a[2] * OSCALE + Cc;
            }
            if (c + 1 < NCLS) {
                const float Cc = d_C[c + 1];
                out[nA * NCLS + c + 1] = a[1] * OSCALE + Cc;
                out[nB * NCLS + c + 1] = a[3] * OSCALE + Cc;
            }
        }
    }
}

// ---------------------------------------------------------------------------
extern "C" void kernel_launch(void* const* d_in, const int* in_sizes, int n_in,
                              void* d_out, int out_size)
{
    const float* probe   = (const float*)d_in[0];
    const float* gallery = (const float*)d_in[1];
    const float* gamma   = (const float*)d_in[2];
    const float* beta    = (const float*)d_in[3];
    const float* W       = (const float*)d_in[4];
    const float* b       = (const float*)d_in[5];
    float* out = (float*)d_out;

    static bool attr_set = false;
    if (!attr_set) {
        cudaFuncSetAttribute(gemm_kernel,
                             cudaFuncAttributeMaxDynamicSharedMemorySize,
                             SMEM_TOTAL);
        attr_set = true;
    }

    stats_build_kernel<<<128 + 1024, 256>>>(probe, gallery, gamma, beta);
    prep_kernel<<<NCLSP, 256>>>(W, b);
    dim3 grid(NCLSP / TNC, NROWS / TM);   // (6, 128)
    gemm_kernel<<<grid, 512, SMEM_TOTAL>>>(out);
}